// round 1
// baseline (speedup 1.0000x reference)
#include <cuda_runtime.h>

#define B_    4
#define N_    512
#define INF_  256
#define OUTF  128
#define HALFF 64
#define EDGEF 16

// ---------------- scratch (no allocation allowed) ----------------
__device__ float g_Wh[B_ * N_ * OUTF];     // 1 MB
__device__ float g_f1[B_ * N_];
__device__ float g_f2[B_ * N_];
__device__ float g_att[B_ * N_ * N_];      // 4 MB raw attention logits

// =================================================================
// Kernel A: Wh = h @ W  (and f1 = Wh@a[:128], f2 = Wh@a[128:])
// grid (64, 4) x 128 threads; 8 rows per CTA.
// =================================================================
__global__ void __launch_bounds__(128) kernA(
    const float* __restrict__ h, const float* __restrict__ W,
    const float* __restrict__ a)
{
    int b  = blockIdx.y;
    int i0 = blockIdx.x * 8;
    int tid = threadIdx.x;                 // = output column d

    __shared__ float h_s[8 * 256];
    __shared__ float a_s[256];
    __shared__ float red[2][4];

    for (int idx = tid; idx < 256; idx += 128) a_s[idx] = a[idx];
    {
        const float4* hg  = (const float4*)(h + ((long)b * N_ + i0) * INF_);
        float4* hs4 = (float4*)h_s;
        for (int idx = tid; idx < 512; idx += 128) hs4[idx] = hg[idx];
    }
    __syncthreads();

    float acc[8];
#pragma unroll
    for (int r = 0; r < 8; r++) acc[r] = 0.f;

    const float* Wp = W + tid;
#pragma unroll 4
    for (int k = 0; k < 256; k++) {
        float w = Wp[k * OUTF];
#pragma unroll
        for (int r = 0; r < 8; r++) acc[r] += h_s[r * 256 + k] * w;
    }

    int lane = tid & 31, wrp = tid >> 5;
    for (int r = 0; r < 8; r++) {
        int row = b * N_ + i0 + r;
        g_Wh[row * OUTF + tid] = acc[r];
        float v1 = acc[r] * a_s[tid];
        float v2 = acc[r] * a_s[128 + tid];
#pragma unroll
        for (int o = 16; o; o >>= 1) {
            v1 += __shfl_down_sync(~0u, v1, o);
            v2 += __shfl_down_sync(~0u, v2, o);
        }
        if (lane == 0) { red[0][wrp] = v1; red[1][wrp] = v2; }
        __syncthreads();
        if (tid == 0) g_f1[row] = red[0][0] + red[0][1] + red[0][2] + red[0][3];
        if (tid == 1) g_f2[row] = red[1][0] + red[1][1] + red[1][2] + red[1][3];
        __syncthreads();
    }
}

// =================================================================
// Kernel B: edge FFN + att logits.  One CTA per (b, i, 64-wide j tile).
//   GEMM1: EH[64x128] = relu(edge[64x16] @ w1 + b1)  -> smem transposed
//   GEMM2: EW[64x64]  = relu(EH @ w2 + b2)           -> out1 + row sums
//   att_raw = leaky(f1[i]+f2[j]) * (64 + sum_c EW)
// grid (8, 512, 4) x 256 threads, 80896 B dynamic smem.
// =================================================================
#define EHT_PITCH 68   // 64 + 4 pad: conflict-free, float4-aligned

__global__ void __launch_bounds__(256) kernB(
    const float* __restrict__ edge,
    const float* __restrict__ w1g, const float* __restrict__ b1g,
    const float* __restrict__ w2g, const float* __restrict__ b2g,
    float* __restrict__ out1)
{
    extern __shared__ float sm[];
    float* w1   = sm;                   // 16*128   = 2048
    float* b1   = w1 + 2048;            // 128
    float* w2   = b1 + 128;             // 128*64   = 8192
    float* b2   = w2 + 8192;            // 64
    float* edg  = b2 + 64;              // 64*16    = 1024
    float* eht  = edg + 1024;           // 128*68   = 8704  (EH transposed)
    float* ssum = eht + 128 * EHT_PITCH;// 64

    int b = blockIdx.z, i = blockIdx.y, jt = blockIdx.x;
    int j0g = jt * 64;
    int tid = threadIdx.x;

    for (int idx = tid; idx < 2048; idx += 256) w1[idx] = w1g[idx];
    for (int idx = tid; idx < 8192; idx += 256) w2[idx] = w2g[idx];
    if (tid < 128)      b1[tid]       = b1g[tid];
    else if (tid < 192) b2[tid - 128] = b2g[tid - 128];
    {
        const float4* eg4 = (const float4*)(edge + ((long)(b * N_ + i) * N_ + j0g) * EDGEF);
        ((float4*)edg)[tid] = eg4[tid];   // 256 float4 = 64x16 floats
    }
    __syncthreads();

    // ---------------- GEMM1 ----------------
    {
        int j = tid & 63, cg = tid >> 6;          // cg: 32-col group
        float ed[16];
        const float4* e4 = (const float4*)(edg + j * 16);
        float4 t0 = e4[0], t1 = e4[1], t2 = e4[2], t3 = e4[3];
        ed[0]=t0.x; ed[1]=t0.y; ed[2]=t0.z; ed[3]=t0.w;
        ed[4]=t1.x; ed[5]=t1.y; ed[6]=t1.z; ed[7]=t1.w;
        ed[8]=t2.x; ed[9]=t2.y; ed[10]=t2.z; ed[11]=t2.w;
        ed[12]=t3.x; ed[13]=t3.y; ed[14]=t3.z; ed[15]=t3.w;

        float acc1[32];
#pragma unroll
        for (int c = 0; c < 32; c++) acc1[c] = b1[cg * 32 + c];
#pragma unroll
        for (int k = 0; k < 16; k++) {
            const float4* w4 = (const float4*)(w1 + k * 128 + cg * 32);
            float ek = ed[k];
#pragma unroll
            for (int q = 0; q < 8; q++) {
                float4 w = w4[q];
                acc1[q*4+0] += ek * w.x;
                acc1[q*4+1] += ek * w.y;
                acc1[q*4+2] += ek * w.z;
                acc1[q*4+3] += ek * w.w;
            }
        }
#pragma unroll
        for (int c = 0; c < 32; c++)
            eht[(cg * 32 + c) * EHT_PITCH + j] = fmaxf(acc1[c], 0.f);
    }
    __syncthreads();

    // ---------------- GEMM2 ----------------
    {
        int tc = tid & 15, tj = tid >> 4;
        int j0 = tj * 4, c0 = tc * 4;
        float acc[16];
#pragma unroll
        for (int jj = 0; jj < 4; jj++)
#pragma unroll
            for (int cc = 0; cc < 4; cc++)
                acc[jj * 4 + cc] = b2[c0 + cc];

#pragma unroll 4
        for (int k = 0; k < 128; k++) {
            float4 eh = *(const float4*)(eht + k * EHT_PITCH + j0);
            float4 w  = *(const float4*)(w2  + k * 64 + c0);
            acc[0]  += eh.x*w.x; acc[1]  += eh.x*w.y; acc[2]  += eh.x*w.z; acc[3]  += eh.x*w.w;
            acc[4]  += eh.y*w.x; acc[5]  += eh.y*w.y; acc[6]  += eh.y*w.z; acc[7]  += eh.y*w.w;
            acc[8]  += eh.z*w.x; acc[9]  += eh.z*w.y; acc[10] += eh.z*w.z; acc[11] += eh.z*w.w;
            acc[12] += eh.w*w.x; acc[13] += eh.w*w.y; acc[14] += eh.w*w.z; acc[15] += eh.w*w.w;
        }

        int orow = (b * N_ + i) * N_ + j0g + j0;
#pragma unroll
        for (int jj = 0; jj < 4; jj++) {
            float4 v;
            v.x = fmaxf(acc[jj*4+0], 0.f);
            v.y = fmaxf(acc[jj*4+1], 0.f);
            v.z = fmaxf(acc[jj*4+2], 0.f);
            v.w = fmaxf(acc[jj*4+3], 0.f);
            *(float4*)(out1 + (long)(orow + jj) * HALFF + c0) = v;
            float s = v.x + v.y + v.z + v.w;
            s += __shfl_down_sync(~0u, s, 8, 16);
            s += __shfl_down_sync(~0u, s, 4, 16);
            s += __shfl_down_sync(~0u, s, 2, 16);
            s += __shfl_down_sync(~0u, s, 1, 16);
            if (tc == 0) ssum[j0 + jj] = s;
        }
    }
    __syncthreads();

    if (tid < 64) {
        float e = g_f1[b * N_ + i] + g_f2[b * N_ + j0g + tid];
        e = e > 0.f ? e : 0.2f * e;                          // LeakyReLU(0.2)
        g_att[(b * N_ + i) * N_ + j0g + tid] = e * (64.f + ssum[tid]);
    }
}

// =================================================================
// Kernel C: normalize / mask / softmax / h' = att@Wh + x / elu
// grid (512, 4) x 256 threads; one CTA per (b, i) row.
// =================================================================
__global__ void __launch_bounds__(256) kernC(
    const int* __restrict__ adj, const float* __restrict__ x,
    float* __restrict__ out0)
{
    int b = blockIdx.y, i = blockIdx.x;
    int row = b * N_ + i;
    int tid = threadIdx.x;

    __shared__ float att_s[512];
    __shared__ float red[8];
    __shared__ float bcast;
    __shared__ float part[128];

    const float* ar   = g_att + (long)row * N_;
    const int*   adjr = adj   + (long)row * N_;

    float v0 = ar[tid], v1 = ar[tid + 256];

    // 1) max of raw logits (pre-mask, matches reference)
    float m = fmaxf(v0, v1);
#pragma unroll
    for (int o = 16; o; o >>= 1) m = fmaxf(m, __shfl_down_sync(~0u, m, o));
    if ((tid & 31) == 0) red[tid >> 5] = m;
    __syncthreads();
    if (tid == 0) {
        float t = red[0];
        for (int k = 1; k < 8; k++) t = fmaxf(t, red[k]);
        bcast = t;
    }
    __syncthreads();
    float scale = 1.f / (fabsf(bcast) + 1e-6f);

    // 2) normalize + mask
    float a0 = adjr[tid]       > 0 ? v0 * scale : -1e6f;
    float a1 = adjr[tid + 256] > 0 ? v1 * scale : -1e6f;

    // 3) masked max for stable softmax
    m = fmaxf(a0, a1);
#pragma unroll
    for (int o = 16; o; o >>= 1) m = fmaxf(m, __shfl_down_sync(~0u, m, o));
    __syncthreads();                       // red reuse
    if ((tid & 31) == 0) red[tid >> 5] = m;
    __syncthreads();
    if (tid == 0) {
        float t = red[0];
        for (int k = 1; k < 8; k++) t = fmaxf(t, red[k]);
        bcast = t;
    }
    __syncthreads();
    float mm = bcast;

    // 4) exp + sum
    float p0 = expf(a0 - mm), p1 = expf(a1 - mm);
    att_s[tid] = p0; att_s[tid + 256] = p1;
    float s = p0 + p1;
#pragma unroll
    for (int o = 16; o; o >>= 1) s += __shfl_down_sync(~0u, s, o);
    __syncthreads();                       // red reuse
    if ((tid & 31) == 0) red[tid >> 5] = s;
    __syncthreads();
    if (tid == 0) {
        float t = 0.f;
        for (int k = 0; k < 8; k++) t += red[k];
        bcast = t;
    }
    __syncthreads();
    float inv = 1.f / bcast;

    // 5) h' = attention @ Wh + x; elu
    int d = tid & 127, half = tid >> 7;
    const float* wh = g_Wh + (long)(b * N_ + half * 256) * OUTF + d;
    float acc = 0.f;
#pragma unroll 8
    for (int j = 0; j < 256; j++) acc += att_s[half * 256 + j] * wh[j * OUTF];
    if (half) part[d] = acc;
    __syncthreads();
    if (!half) {
        float hp = (acc + part[d]) * inv + x[(long)row * OUTF + d];
        out0[(long)row * OUTF + d] = hp > 0.f ? hp : expf(hp) - 1.f;
    }
}

// =================================================================
extern "C" void kernel_launch(void* const* d_in, const int* in_sizes, int n_in,
                              void* d_out, int out_size)
{
    const float* h    = (const float*)d_in[0];
    const int*   adj  = (const int*)  d_in[1];
    const float* edge = (const float*)d_in[2];
    const float* x    = (const float*)d_in[3];
    const float* W    = (const float*)d_in[4];
    const float* a    = (const float*)d_in[5];
    const float* w1   = (const float*)d_in[6];
    const float* b1   = (const float*)d_in[7];
    const float* w2   = (const float*)d_in[8];
    const float* b2   = (const float*)d_in[9];

    float* out0 = (float*)d_out;                 // elu(h') : 4*512*128
    float* out1 = out0 + B_ * N_ * OUTF;         // edge_w  : 4*512*512*64

    const int smemB = (2048 + 128 + 8192 + 64 + 1024 + 128 * EHT_PITCH + 64) * 4;
    cudaFuncSetAttribute(kernB, cudaFuncAttributeMaxDynamicSharedMemorySize, smemB);

    kernA<<<dim3(64, 4), 128>>>(h, W, a);
    kernB<<<dim3(8, 512, 4), 256, smemB>>>(edge, w1, b1, w2, b2, out1);
    kernC<<<dim3(512, 4), 256>>>(adj, x, out0);
}

// round 3
// speedup vs baseline: 2.1460x; 2.1460x over previous
#include <cuda_runtime.h>
#include <cuda_bf16.h>

#define B_    4
#define N_    512
#define INF_  256
#define OUTF  128
#define HALFF 64
#define EDGEF 16

// ---------------- scratch ----------------
__device__ float g_Wh[B_ * N_ * OUTF];
__device__ float g_f1[B_ * N_];
__device__ float g_f2[B_ * N_];
__device__ float g_att[B_ * N_ * N_];

// ---------------- helpers ----------------
__device__ __forceinline__ unsigned f2bf(float v) {
    return (unsigned)__bfloat16_as_ushort(__float2bfloat16_rn(v));
}
__device__ __forceinline__ float bfu2f(unsigned u) {
    return __bfloat162float(__ushort_as_bfloat16((unsigned short)u));
}
// split v into bf16 hi + bf16 lo (v ~= hi + lo)
__device__ __forceinline__ void split2(float v, unsigned& hi, unsigned& lo) {
    hi = f2bf(v);
    lo = f2bf(v - bfu2f(hi));
}
// pack two floats' bf16(hi) and bf16(lo) into bf16x2 regs (x -> low half)
__device__ __forceinline__ void splitpack(float x, float y, unsigned& h, unsigned& l) {
    unsigned hx, lx, hy, ly;
    split2(x, hx, lx); split2(y, hy, ly);
    h = hx | (hy << 16);
    l = lx | (ly << 16);
}

__device__ __forceinline__ void mma16816(float* c, const unsigned* a, const unsigned* b) {
    asm volatile(
        "mma.sync.aligned.m16n8k16.row.col.f32.bf16.bf16.f32 "
        "{%0,%1,%2,%3}, {%4,%5,%6,%7}, {%8,%9}, {%0,%1,%2,%3};"
        : "+f"(c[0]), "+f"(c[1]), "+f"(c[2]), "+f"(c[3])
        : "r"(a[0]), "r"(a[1]), "r"(a[2]), "r"(a[3]), "r"(b[0]), "r"(b[1]));
}

// =================================================================
// Kernel A: Wh = h @ W, f1 = Wh@a[:128], f2 = Wh@a[128:]
// grid (128, 4) x 128 threads; 4 rows per CTA, deep unroll for MLP.
// =================================================================
__global__ void __launch_bounds__(128) kernA(
    const float* __restrict__ h, const float* __restrict__ W,
    const float* __restrict__ a)
{
    int b = blockIdx.y, i0 = blockIdx.x * 4, tid = threadIdx.x;
    __shared__ float h_s[4 * 256];
    __shared__ float a_s[256];
    __shared__ float red[2][4];

    for (int idx = tid; idx < 256; idx += 128) a_s[idx] = a[idx];
    {
        const float4* hg = (const float4*)(h + ((long)b * N_ + i0) * INF_);
        float4* hs = (float4*)h_s;
        for (int idx = tid; idx < 256; idx += 128) hs[idx] = hg[idx];
    }
    __syncthreads();

    float acc[4] = {0.f, 0.f, 0.f, 0.f};
    const float* Wp = W + tid;
#pragma unroll 16
    for (int k = 0; k < 256; k++) {
        float w = Wp[k * OUTF];
        acc[0] += h_s[k] * w;
        acc[1] += h_s[256 + k] * w;
        acc[2] += h_s[512 + k] * w;
        acc[3] += h_s[768 + k] * w;
    }

    int lane = tid & 31, wrp = tid >> 5;
    for (int r = 0; r < 4; r++) {
        int row = b * N_ + i0 + r;
        g_Wh[row * OUTF + tid] = acc[r];
        float v1 = acc[r] * a_s[tid];
        float v2 = acc[r] * a_s[128 + tid];
#pragma unroll
        for (int o = 16; o; o >>= 1) {
            v1 += __shfl_down_sync(~0u, v1, o);
            v2 += __shfl_down_sync(~0u, v2, o);
        }
        if (lane == 0) { red[0][wrp] = v1; red[1][wrp] = v2; }
        __syncthreads();
        if (tid == 0) g_f1[row] = red[0][0] + red[0][1] + red[0][2] + red[0][3];
        if (tid == 1) g_f2[row] = red[1][0] + red[1][1] + red[1][2] + red[1][3];
        __syncthreads();
    }
}

// =================================================================
// Kernel B: edge FFN via mma.sync bf16 3-term + att logits.
// One CTA (256 thr, 8 warps) per (b,i); 4 j-tiles of 128; each warp
// owns one 16-row m-tile. EH stays entirely in registers (GEMM1 C
// fragments == GEMM2 A fragments). No syncs inside the j-loop.
// =================================================================
#define W1P 9
#define W2P 68

__global__ void __launch_bounds__(256) kernB(
    const float* __restrict__ edge,
    const float* __restrict__ w1g, const float* __restrict__ b1g,
    const float* __restrict__ w2g, const float* __restrict__ b2g,
    float* __restrict__ out1)
{
    __shared__ unsigned w1h[128 * W1P], w1l[128 * W1P];
    __shared__ unsigned w2h[64 * W2P],  w2l[64 * W2P];
    __shared__ float b1s[128], b2s[64];

    int tid = threadIdx.x, wid = tid >> 5, lane = tid & 31;
    int g = lane >> 2, c = lane & 3;
    int b = blockIdx.y, i = blockIdx.x;

    // ---- stage weights (B-fragment pre-pack: w[n][kp] = bf16x2(w[2kp][n], w[2kp+1][n])) ----
    for (int idx = tid; idx < 1024; idx += 256) {
        int n = idx & 127, kp = idx >> 7;
        unsigned h, l;
        splitpack(w1g[(2 * kp) * OUTF + n], w1g[(2 * kp + 1) * OUTF + n], h, l);
        w1h[n * W1P + kp] = h; w1l[n * W1P + kp] = l;
    }
    for (int idx = tid; idx < 4096; idx += 256) {
        int n = idx & 63, kp = idx >> 6;
        unsigned h, l;
        splitpack(w2g[(2 * kp) * HALFF + n], w2g[(2 * kp + 1) * HALFF + n], h, l);
        w2h[n * W2P + kp] = h; w2l[n * W2P + kp] = l;
    }
    if (tid < 128)      b1s[tid]       = b1g[tid];
    else if (tid < 192) b2s[tid - 128] = b2g[tid - 128];
    __syncthreads();

    float f1v = g_f1[b * N_ + i];
    long erow = ((long)(b * N_ + i)) * N_;

    for (int t = 0; t < 4; t++) {
        int jt = t * 128 + wid * 16;          // warp's 16-row block
        const float* ep = edge + (erow + jt) * EDGEF;

        // ---- load edge A fragments directly from gmem, split hi/lo ----
        unsigned ah[4], al[4];
        {
            float2 v0 = *(const float2*)(ep + (g)     * EDGEF + 2 * c);
            float2 v1 = *(const float2*)(ep + (g + 8) * EDGEF + 2 * c);
            float2 v2 = *(const float2*)(ep + (g)     * EDGEF + 2 * c + 8);
            float2 v3 = *(const float2*)(ep + (g + 8) * EDGEF + 2 * c + 8);
            splitpack(v0.x, v0.y, ah[0], al[0]);
            splitpack(v1.x, v1.y, ah[1], al[1]);
            splitpack(v2.x, v2.y, ah[2], al[2]);
            splitpack(v3.x, v3.y, ah[3], al[3]);
        }

        // ---- GEMM1: EH[16x128] = edge @ w1 (3-term) ----
        float c1[16][4];
#pragma unroll
        for (int nt = 0; nt < 16; nt++) {
            c1[nt][0] = c1[nt][1] = c1[nt][2] = c1[nt][3] = 0.f;
            int n = nt * 8 + g;
            unsigned bh[2] = { w1h[n * W1P + c], w1h[n * W1P + c + 4] };
            unsigned bl[2] = { w1l[n * W1P + c], w1l[n * W1P + c + 4] };
            mma16816(c1[nt], ah, bh);
            mma16816(c1[nt], ah, bl);
            mma16816(c1[nt], al, bh);
        }

        // ---- bias + relu + split -> GEMM2 A fragments in registers ----
        unsigned ehh[16][2], ehl[16][2];
#pragma unroll
        for (int nt = 0; nt < 16; nt++) {
            float bx = b1s[nt * 8 + 2 * c], by = b1s[nt * 8 + 2 * c + 1];
            float r0 = fmaxf(c1[nt][0] + bx, 0.f);
            float r1 = fmaxf(c1[nt][1] + by, 0.f);
            float r2 = fmaxf(c1[nt][2] + bx, 0.f);
            float r3 = fmaxf(c1[nt][3] + by, 0.f);
            splitpack(r0, r1, ehh[nt][0], ehl[nt][0]);
            splitpack(r2, r3, ehh[nt][1], ehl[nt][1]);
        }

        // ---- GEMM2: EW[16x64] = EH @ w2 (8 K-steps x 3 terms) ----
        float c2[8][4];
#pragma unroll
        for (int nt = 0; nt < 8; nt++)
            c2[nt][0] = c2[nt][1] = c2[nt][2] = c2[nt][3] = 0.f;
#pragma unroll
        for (int s = 0; s < 8; s++) {
            unsigned Ah[4] = { ehh[2*s][0], ehh[2*s][1], ehh[2*s+1][0], ehh[2*s+1][1] };
            unsigned Al[4] = { ehl[2*s][0], ehl[2*s][1], ehl[2*s+1][0], ehl[2*s+1][1] };
#pragma unroll
            for (int nt = 0; nt < 8; nt++) {
                int n = nt * 8 + g;
                unsigned bh[2] = { w2h[n * W2P + 8 * s + c], w2h[n * W2P + 8 * s + c + 4] };
                unsigned bl[2] = { w2l[n * W2P + 8 * s + c], w2l[n * W2P + 8 * s + c + 4] };
                mma16816(c2[nt], Ah, bh);
                mma16816(c2[nt], Ah, bl);
                mma16816(c2[nt], Al, bh);
            }
        }

        // ---- epilogue: bias + relu, write out1, fold row sums into att ----
        float sum_g = 0.f, sum_g8 = 0.f;
        float* op = out1 + (erow + jt) * HALFF;
#pragma unroll
        for (int nt = 0; nt < 8; nt++) {
            float bx = b2s[nt * 8 + 2 * c], by = b2s[nt * 8 + 2 * c + 1];
            float r0 = fmaxf(c2[nt][0] + bx, 0.f);
            float r1 = fmaxf(c2[nt][1] + by, 0.f);
            float r2 = fmaxf(c2[nt][2] + bx, 0.f);
            float r3 = fmaxf(c2[nt][3] + by, 0.f);
            sum_g  += r0 + r1;
            sum_g8 += r2 + r3;
            *(float2*)(op + (long)(g)     * HALFF + nt * 8 + 2 * c) = make_float2(r0, r1);
            *(float2*)(op + (long)(g + 8) * HALFF + nt * 8 + 2 * c) = make_float2(r2, r3);
        }
        sum_g  += __shfl_xor_sync(~0u, sum_g, 1);
        sum_g  += __shfl_xor_sync(~0u, sum_g, 2);
        sum_g8 += __shfl_xor_sync(~0u, sum_g8, 1);
        sum_g8 += __shfl_xor_sync(~0u, sum_g8, 2);
        if (c == 0) {
            int j = jt + g;
            float e = f1v + g_f2[b * N_ + j];
            e = e > 0.f ? e : 0.2f * e;
            g_att[erow + j] = e * (64.f + sum_g);
            j += 8;
            float e2 = f1v + g_f2[b * N_ + j];
            e2 = e2 > 0.f ? e2 : 0.2f * e2;
            g_att[erow + j] = e2 * (64.f + sum_g8);
        }
    }
}

// =================================================================
// Kernel C: normalize / mask / softmax / h' = att@Wh + x / elu
// =================================================================
__global__ void __launch_bounds__(256) kernC(
    const int* __restrict__ adj, const float* __restrict__ x,
    float* __restrict__ out0)
{
    int b = blockIdx.y, i = blockIdx.x;
    int row = b * N_ + i;
    int tid = threadIdx.x;

    __shared__ float att_s[512];
    __shared__ float red[8];
    __shared__ float bcast;
    __shared__ float part[128];

    const float* ar   = g_att + (long)row * N_;
    const int*   adjr = adj   + (long)row * N_;

    float v0 = ar[tid], v1 = ar[tid + 256];

    float m = fmaxf(v0, v1);
#pragma unroll
    for (int o = 16; o; o >>= 1) m = fmaxf(m, __shfl_down_sync(~0u, m, o));
    if ((tid & 31) == 0) red[tid >> 5] = m;
    __syncthreads();
    if (tid == 0) {
        float t = red[0];
        for (int k = 1; k < 8; k++) t = fmaxf(t, red[k]);
        bcast = t;
    }
    __syncthreads();
    float scale = 1.f / (fabsf(bcast) + 1e-6f);

    float a0 = adjr[tid]       > 0 ? v0 * scale : -1e6f;
    float a1 = adjr[tid + 256] > 0 ? v1 * scale : -1e6f;

    m = fmaxf(a0, a1);
#pragma unroll
    for (int o = 16; o; o >>= 1) m = fmaxf(m, __shfl_down_sync(~0u, m, o));
    __syncthreads();
    if ((tid & 31) == 0) red[tid >> 5] = m;
    __syncthreads();
    if (tid == 0) {
        float t = red[0];
        for (int k = 1; k < 8; k++) t = fmaxf(t, red[k]);
        bcast = t;
    }
    __syncthreads();
    float mm = bcast;

    float p0 = expf(a0 - mm), p1 = expf(a1 - mm);
    att_s[tid] = p0; att_s[tid + 256] = p1;
    float s = p0 + p1;
#pragma unroll
    for (int o = 16; o; o >>= 1) s += __shfl_down_sync(~0u, s, o);
    __syncthreads();
    if ((tid & 31) == 0) red[tid >> 5] = s;
    __syncthreads();
    if (tid == 0) {
        float t = 0.f;
        for (int k = 0; k < 8; k++) t += red[k];
        bcast = t;
    }
    __syncthreads();
    float inv = 1.f / bcast;

    int d = tid & 127, half = tid >> 7;
    const float* wh = g_Wh + (long)(b * N_ + half * 256) * OUTF + d;
    float acc = 0.f;
#pragma unroll 8
    for (int j = 0; j < 256; j++) acc += att_s[half * 256 + j] * wh[j * OUTF];
    if (half) part[d] = acc;
    __syncthreads();
    if (!half) {
        float hp = (acc + part[d]) * inv + x[(long)row * OUTF + d];
        out0[(long)row * OUTF + d] = hp > 0.f ? hp : expf(hp) - 1.f;
    }
}

// =================================================================
extern "C" void kernel_launch(void* const* d_in, const int* in_sizes, int n_in,
                              void* d_out, int out_size)
{
    const float* h    = (const float*)d_in[0];
    const int*   adj  = (const int*)  d_in[1];
    const float* edge = (const float*)d_in[2];
    const float* x    = (const float*)d_in[3];
    const float* W    = (const float*)d_in[4];
    const float* a    = (const float*)d_in[5];
    const float* w1   = (const float*)d_in[6];
    const float* b1   = (const float*)d_in[7];
    const float* w2   = (const float*)d_in[8];
    const float* b2   = (const float*)d_in[9];

    float* out0 = (float*)d_out;
    float* out1 = out0 + B_ * N_ * OUTF;

    kernA<<<dim3(128, 4), 128>>>(h, W, a);
    kernB<<<dim3(512, 4), 256>>>(edge, w1, b1, w2, b2, out1);
    kernC<<<dim3(512, 4), 256>>>(adj, x, out0);
}

// round 4
// speedup vs baseline: 3.0446x; 1.4187x over previous
#include <cuda_runtime.h>
#include <cuda_bf16.h>

#define B_    4
#define N_    512
#define INF_  256
#define OUTF  128
#define HALFF 64
#define EDGEF 16

// ---------------- scratch ----------------
__device__ float g_Wh[B_ * N_ * OUTF];
__device__ float g_f1[B_ * N_];
__device__ float g_f2[B_ * N_];
__device__ float g_att[B_ * N_ * N_];

// ---------------- helpers ----------------
__device__ __forceinline__ unsigned f2bf(float v) {
    return (unsigned)__bfloat16_as_ushort(__float2bfloat16_rn(v));
}
__device__ __forceinline__ float bfu2f(unsigned u) {
    return __bfloat162float(__ushort_as_bfloat16((unsigned short)u));
}
__device__ __forceinline__ void split2(float v, unsigned& hi, unsigned& lo) {
    hi = f2bf(v);
    lo = f2bf(v - bfu2f(hi));
}
__device__ __forceinline__ void splitpack(float x, float y, unsigned& h, unsigned& l) {
    unsigned hx, lx, hy, ly;
    split2(x, hx, lx); split2(y, hy, ly);
    h = hx | (hy << 16);
    l = lx | (ly << 16);
}

__device__ __forceinline__ void mma16816(float* c, const unsigned* a, const unsigned* b) {
    asm volatile(
        "mma.sync.aligned.m16n8k16.row.col.f32.bf16.bf16.f32 "
        "{%0,%1,%2,%3}, {%4,%5,%6,%7}, {%8,%9}, {%0,%1,%2,%3};"
        : "+f"(c[0]), "+f"(c[1]), "+f"(c[2]), "+f"(c[3])
        : "r"(a[0]), "r"(a[1]), "r"(a[2]), "r"(a[3]), "r"(b[0]), "r"(b[1]));
}

// =================================================================
// Kernel A: Wh = h @ W, f1 = Wh@a[:128], f2 = Wh@a[128:]
// grid (64, 4) x 128 threads; 8 rows per CTA, unroll 16.
// =================================================================
__global__ void __launch_bounds__(128) kernA(
    const float* __restrict__ h, const float* __restrict__ W,
    const float* __restrict__ a)
{
    int b = blockIdx.y, i0 = blockIdx.x * 8, tid = threadIdx.x;
    __shared__ float h_s[8 * 256];
    __shared__ float a_s[256];
    __shared__ float red[2][4];

    for (int idx = tid; idx < 256; idx += 128) a_s[idx] = a[idx];
    {
        const float4* hg = (const float4*)(h + ((long)b * N_ + i0) * INF_);
        float4* hs = (float4*)h_s;
        for (int idx = tid; idx < 512; idx += 128) hs[idx] = hg[idx];
    }
    __syncthreads();

    float acc[8];
#pragma unroll
    for (int r = 0; r < 8; r++) acc[r] = 0.f;

    const float* Wp = W + tid;
#pragma unroll 16
    for (int k = 0; k < 256; k++) {
        float w = Wp[k * OUTF];
#pragma unroll
        for (int r = 0; r < 8; r++) acc[r] += h_s[r * 256 + k] * w;
    }

    int lane = tid & 31, wrp = tid >> 5;
    for (int r = 0; r < 8; r++) {
        int row = b * N_ + i0 + r;
        g_Wh[row * OUTF + tid] = acc[r];
        float v1 = acc[r] * a_s[tid];
        float v2 = acc[r] * a_s[128 + tid];
#pragma unroll
        for (int o = 16; o; o >>= 1) {
            v1 += __shfl_down_sync(~0u, v1, o);
            v2 += __shfl_down_sync(~0u, v2, o);
        }
        if (lane == 0) { red[0][wrp] = v1; red[1][wrp] = v2; }
        __syncthreads();
        if (tid == 0) g_f1[row] = red[0][0] + red[0][1] + red[0][2] + red[0][3];
        if (tid == 1) g_f2[row] = red[1][0] + red[1][1] + red[1][2] + red[1][3];
        __syncthreads();
    }
}

// =================================================================
// Kernel B: edge FFN via mma.sync bf16 3-term, GEMM1 fused into
// GEMM2 per 16-wide K-chunk (low register footprint -> 2 CTAs/SM).
// One CTA (8 warps) per (b,i); 4 j-tiles of 128; warp owns 16 rows.
// =================================================================
#define W1P 9
#define W2P 68

__global__ void __launch_bounds__(256, 2) kernB(
    const float* __restrict__ edge,
    const float* __restrict__ w1g, const float* __restrict__ b1g,
    const float* __restrict__ w2g, const float* __restrict__ b2g,
    float* __restrict__ out1)
{
    __shared__ unsigned w1h[128 * W1P], w1l[128 * W1P];
    __shared__ unsigned w2h[64 * W2P],  w2l[64 * W2P];
    __shared__ float b1s[128], b2s[64];

    int tid = threadIdx.x, wid = tid >> 5, lane = tid & 31;
    int g = lane >> 2, c = lane & 3;
    int b = blockIdx.y, i = blockIdx.x;

    // stage weights as pre-packed B fragments (bf16x2 over K pairs), hi/lo
    for (int idx = tid; idx < 1024; idx += 256) {
        int n = idx & 127, kp = idx >> 7;
        unsigned h, l;
        splitpack(w1g[(2 * kp) * OUTF + n], w1g[(2 * kp + 1) * OUTF + n], h, l);
        w1h[n * W1P + kp] = h; w1l[n * W1P + kp] = l;
    }
    for (int idx = tid; idx < 4096; idx += 256) {
        int n = idx & 63, kp = idx >> 6;
        unsigned h, l;
        splitpack(w2g[(2 * kp) * HALFF + n], w2g[(2 * kp + 1) * HALFF + n], h, l);
        w2h[n * W2P + kp] = h; w2l[n * W2P + kp] = l;
    }
    if (tid < 128)      b1s[tid]       = b1g[tid];
    else if (tid < 192) b2s[tid - 128] = b2g[tid - 128];
    __syncthreads();

    float f1v = g_f1[b * N_ + i];
    long erow = ((long)(b * N_ + i)) * N_;

    for (int t = 0; t < 4; t++) {
        int jt = t * 128 + wid * 16;
        const float* ep = edge + (erow + jt) * EDGEF;

        // edge A fragments straight from gmem, hi/lo split
        unsigned ah[4], al[4];
        {
            float2 v0 = *(const float2*)(ep + (g)     * EDGEF + 2 * c);
            float2 v1 = *(const float2*)(ep + (g + 8) * EDGEF + 2 * c);
            float2 v2 = *(const float2*)(ep + (g)     * EDGEF + 2 * c + 8);
            float2 v3 = *(const float2*)(ep + (g + 8) * EDGEF + 2 * c + 8);
            splitpack(v0.x, v0.y, ah[0], al[0]);
            splitpack(v1.x, v1.y, ah[1], al[1]);
            splitpack(v2.x, v2.y, ah[2], al[2]);
            splitpack(v3.x, v3.y, ah[3], al[3]);
        }

        float c2[8][4];
#pragma unroll
        for (int nt = 0; nt < 8; nt++)
            c2[nt][0] = c2[nt][1] = c2[nt][2] = c2[nt][3] = 0.f;

        // fused: per K-chunk s, build EH cols [16s,16s+16) then consume them
#pragma unroll
        for (int s = 0; s < 8; s++) {
            unsigned Ah[4], Al[4];
#pragma unroll
            for (int q = 0; q < 2; q++) {
                int nt1 = 2 * s + q;
                float c1[4] = {0.f, 0.f, 0.f, 0.f};
                int n = nt1 * 8 + g;
                unsigned bh[2] = { w1h[n * W1P + c], w1h[n * W1P + c + 4] };
                unsigned bl[2] = { w1l[n * W1P + c], w1l[n * W1P + c + 4] };
                mma16816(c1, ah, bh);
                mma16816(c1, ah, bl);
                mma16816(c1, al, bh);
                float bx = b1s[nt1 * 8 + 2 * c], by = b1s[nt1 * 8 + 2 * c + 1];
                float r0 = fmaxf(c1[0] + bx, 0.f);
                float r1 = fmaxf(c1[1] + by, 0.f);
                float r2 = fmaxf(c1[2] + bx, 0.f);
                float r3 = fmaxf(c1[3] + by, 0.f);
                splitpack(r0, r1, Ah[2 * q],     Al[2 * q]);
                splitpack(r2, r3, Ah[2 * q + 1], Al[2 * q + 1]);
            }
#pragma unroll
            for (int nt = 0; nt < 8; nt++) {
                int n = nt * 8 + g;
                unsigned bh[2] = { w2h[n * W2P + 8 * s + c], w2h[n * W2P + 8 * s + c + 4] };
                unsigned bl[2] = { w2l[n * W2P + 8 * s + c], w2l[n * W2P + 8 * s + c + 4] };
                mma16816(c2[nt], Ah, bh);
                mma16816(c2[nt], Ah, bl);
                mma16816(c2[nt], Al, bh);
            }
        }

        // epilogue: bias + relu, write out1, fold row sums into att logits
        float sum_g = 0.f, sum_g8 = 0.f;
        float* op = out1 + (erow + jt) * HALFF;
#pragma unroll
        for (int nt = 0; nt < 8; nt++) {
            float bx = b2s[nt * 8 + 2 * c], by = b2s[nt * 8 + 2 * c + 1];
            float r0 = fmaxf(c2[nt][0] + bx, 0.f);
            float r1 = fmaxf(c2[nt][1] + by, 0.f);
            float r2 = fmaxf(c2[nt][2] + bx, 0.f);
            float r3 = fmaxf(c2[nt][3] + by, 0.f);
            sum_g  += r0 + r1;
            sum_g8 += r2 + r3;
            *(float2*)(op + (long)(g)     * HALFF + nt * 8 + 2 * c) = make_float2(r0, r1);
            *(float2*)(op + (long)(g + 8) * HALFF + nt * 8 + 2 * c) = make_float2(r2, r3);
        }
        sum_g  += __shfl_xor_sync(~0u, sum_g, 1);
        sum_g  += __shfl_xor_sync(~0u, sum_g, 2);
        sum_g8 += __shfl_xor_sync(~0u, sum_g8, 1);
        sum_g8 += __shfl_xor_sync(~0u, sum_g8, 2);
        if (c == 0) {
            int j = jt + g;
            float e = f1v + g_f2[b * N_ + j];
            e = e > 0.f ? e : 0.2f * e;
            g_att[erow + j] = e * (64.f + sum_g);
            j += 8;
            float e2 = f1v + g_f2[b * N_ + j];
            e2 = e2 > 0.f ? e2 : 0.2f * e2;
            g_att[erow + j] = e2 * (64.f + sum_g8);
        }
    }
}

// =================================================================
// Kernel C: normalize / mask / softmax / h' = att@Wh + x / elu
// 4 rows per CTA -> Wh L2 traffic shared 4x.
// grid (128, 4) x 256 threads.
// =================================================================
__global__ void __launch_bounds__(256) kernC(
    const int* __restrict__ adj, const float* __restrict__ x,
    float* __restrict__ out0)
{
    int b = blockIdx.y, i0 = blockIdx.x * 4;
    int tid = threadIdx.x;

    __shared__ float att_s[4][512];
    __shared__ float red[8];
    __shared__ float bcast;
    __shared__ float inv4[4];
    __shared__ float part[4][128];

    for (int r = 0; r < 4; r++) {
        int row = b * N_ + i0 + r;
        const float* ar   = g_att + (long)row * N_;
        const int*   adjr = adj   + (long)row * N_;

        float v0 = ar[tid], v1 = ar[tid + 256];

        float m = fmaxf(v0, v1);
#pragma unroll
        for (int o = 16; o; o >>= 1) m = fmaxf(m, __shfl_down_sync(~0u, m, o));
        if ((tid & 31) == 0) red[tid >> 5] = m;
        __syncthreads();
        if (tid == 0) {
            float t = red[0];
            for (int k = 1; k < 8; k++) t = fmaxf(t, red[k]);
            bcast = t;
        }
        __syncthreads();
        float scale = 1.f / (fabsf(bcast) + 1e-6f);

        float a0 = adjr[tid]       > 0 ? v0 * scale : -1e6f;
        float a1 = adjr[tid + 256] > 0 ? v1 * scale : -1e6f;

        m = fmaxf(a0, a1);
#pragma unroll
        for (int o = 16; o; o >>= 1) m = fmaxf(m, __shfl_down_sync(~0u, m, o));
        __syncthreads();
        if ((tid & 31) == 0) red[tid >> 5] = m;
        __syncthreads();
        if (tid == 0) {
            float t = red[0];
            for (int k = 1; k < 8; k++) t = fmaxf(t, red[k]);
            bcast = t;
        }
        __syncthreads();
        float mm = bcast;

        float p0 = expf(a0 - mm), p1 = expf(a1 - mm);
        att_s[r][tid] = p0; att_s[r][tid + 256] = p1;
        float s = p0 + p1;
#pragma unroll
        for (int o = 16; o; o >>= 1) s += __shfl_down_sync(~0u, s, o);
        __syncthreads();
        if ((tid & 31) == 0) red[tid >> 5] = s;
        __syncthreads();
        if (tid == 0) {
            float t = 0.f;
            for (int k = 0; k < 8; k++) t += red[k];
            bcast = t;
        }
        __syncthreads();
        if (tid == 0) inv4[r] = 1.f / bcast;
        __syncthreads();
    }

    // h' = attention @ Wh + x; one Wh read serves 4 rows
    int d = tid & 127, half = tid >> 7;
    const float* wh = g_Wh + (long)(b * N_ + half * 256) * OUTF + d;
    float acc[4] = {0.f, 0.f, 0.f, 0.f};
#pragma unroll 8
    for (int j = 0; j < 256; j++) {
        float wv = wh[j * OUTF];
        int jj = half * 256 + j;
        acc[0] += att_s[0][jj] * wv;
        acc[1] += att_s[1][jj] * wv;
        acc[2] += att_s[2][jj] * wv;
        acc[3] += att_s[3][jj] * wv;
    }
    if (half) {
#pragma unroll
        for (int r = 0; r < 4; r++) part[r][d] = acc[r];
    }
    __syncthreads();
    if (!half) {
#pragma unroll
        for (int r = 0; r < 4; r++) {
            int row = b * N_ + i0 + r;
            float hp = (acc[r] + part[r][d]) * inv4[r] + x[(long)row * OUTF + d];
            out0[(long)row * OUTF + d] = hp > 0.f ? hp : expf(hp) - 1.f;
        }
    }
}

// =================================================================
extern "C" void kernel_launch(void* const* d_in, const int* in_sizes, int n_in,
                              void* d_out, int out_size)
{
    const float* h    = (const float*)d_in[0];
    const int*   adj  = (const int*)  d_in[1];
    const float* edge = (const float*)d_in[2];
    const float* x    = (const float*)d_in[3];
    const float* W    = (const float*)d_in[4];
    const float* a    = (const float*)d_in[5];
    const float* w1   = (const float*)d_in[6];
    const float* b1   = (const float*)d_in[7];
    const float* w2   = (const float*)d_in[8];
    const float* b2   = (const float*)d_in[9];

    float* out0 = (float*)d_out;
    float* out1 = out0 + B_ * N_ * OUTF;

    kernA<<<dim3(64, 4), 128>>>(h, W, a);
    kernB<<<dim3(512, 4), 256>>>(edge, w1, b1, w2, b2, out1);
    kernC<<<dim3(128, 4), 256>>>(adj, x, out0);
}